// round 17
// baseline (speedup 1.0000x reference)
#include <cuda_runtime.h>

#define NT 128
#define NH 8
#define NL 3
#define LOG2E 1.4426950408889634f

#define O_WK  0
#define O_WQ  24
#define O_WV  48
#define O_WP  72
#define O_BP  96
#define O_W1  99
#define O_B1  111
#define O_W2  123
#define O_B2  135
#define O_WLM 138
#define O_BLM 139
#define NWTS  140

__device__ __forceinline__ float ex2(float x) {
    float y;
    asm("ex2.approx.ftz.f32 %0, %1;" : "=f"(y) : "f"(x));
    return y;
}

__device__ __forceinline__ float redux_max_nn(float x) {
    unsigned r;
    asm("redux.sync.max.u32 %0, %1, 0xffffffff;" : "=r"(r) : "r"(__float_as_uint(x)));
    return __uint_as_float(r);
}

struct OS { float m, d, n; };
__device__ __forceinline__ OS comb(OS a, OS b) {
    float mx = fmaxf(a.m, b.m);
    float mn = fminf(a.m, b.m);
    float e  = ex2(mn - mx);
    bool  bl = a.m < b.m;
    float sa = bl ? e : 1.0f;
    float sb = bl ? 1.0f : e;
    OS r; r.m = mx; r.d = fmaf(a.d, sa, b.d * sb); r.n = fmaf(a.n, sa, b.n * sb);
    return r;
}

__global__ __launch_bounds__(256) void cat_kernel(
    const float* __restrict__ X,
    const float* __restrict__ wk, const float* __restrict__ wq, const float* __restrict__ wv,
    const float* __restrict__ Wp, const float* __restrict__ bp,
    const float* __restrict__ W1, const float* __restrict__ b1,
    const float* __restrict__ W2, const float* __restrict__ b2,
    const float* __restrict__ w_lm, const float* __restrict__ b_lm,
    float* __restrict__ out)
{
    __shared__ float W[NWTS];
    __shared__ float ps[NH][NT];   // [warp=head][position] partial y (cf-scaled)
    __shared__ float xs[NT];       // x between layers

    const int tid   = threadIdx.x;
    const int wr    = tid >> 5;    // 0..7: head id
    const int lid   = tid & 31;
    const int batch = blockIdx.x;

    // X load first; weight staging overlaps the latency
    float4 xv = reinterpret_cast<const float4*>(X + batch * NT)[lid];

    if (tid < NWTS) {
        int i = tid;
        float v;
        if      (i < 24)  v = wk[i];
        else if (i < 48)  v = wq[i - 24];
        else if (i < 72)  v = wv[i - 48];
        else if (i < 96)  v = Wp[i - 72];
        else if (i < 99)  v = bp[i - 96];
        else if (i < 111) v = W1[i - 99];
        else if (i < 123) v = b1[i - 111];
        else if (i < 135) v = W2[i - 123];
        else if (i < 138) v = b2[i - 135];
        else if (i == 138) v = w_lm[0];
        else               v = b_lm[0];
        W[i] = v;
    }
    __syncthreads();

    // scan-side hoists (per head)
    float c_r[NL], coef_r[NL], ca_r[NL];
    #pragma unroll
    for (int l = 0; l < NL; ++l) {
        float cc = W[O_WK + l*NH + wr] * W[O_WQ + l*NH + wr] * LOG2E;
        c_r[l]    = cc;
        ca_r[l]   = fabsf(cc);
        coef_r[l] = W[O_WV + l*NH + wr] * W[O_WP + l*NH + wr];
    }

    // epilogue-side hoists (used by threads < NT; registers are free at this occupancy)
    float bp_e[NL], b2_e[NL], w1_e[NL][4], b1_e[NL][4], w2_e[NL][4];
    #pragma unroll
    for (int l = 0; l < NL; ++l) {
        bp_e[l] = W[O_BP + l];
        b2_e[l] = W[O_B2 + l];
        #pragma unroll
        for (int k = 0; k < 4; ++k) {
            w1_e[l][k] = W[O_W1 + l*4 + k];
            b1_e[l][k] = W[O_B1 + l*4 + k];
            w2_e[l][k] = W[O_W2 + l*4 + k];
        }
    }
    const float wlm = W[O_WLM], blm = W[O_BLM];

    float x0 = xv.x, x1 = xv.y, x2 = xv.z, x3 = xv.w;

    #pragma unroll
    for (int l = 0; l < NL; ++l) {
        const float u0 = x0*x0, u1 = x1*x1, u2 = x2*x2, u3 = x3*x3;

        // single redux: umx. Guard |c|*umx < 120 implies |c|*(umx-umn) < 120 since umn >= 0.
        const float umx = redux_max_nn(fmaxf(fmaxf(u0, u1), fmaxf(u2, u3)));

        const float ch = c_r[l];
        const float cf = coef_r[l];
        // cf folded into numerator inputs (off critical path)
        const float xc0 = x0 * cf, xc1 = x1 * cf, xc2 = x2 * cf, xc3 = x3 * cf;

        float py0, py1, py2, py3;

        if (ca_r[l] * umx < 120.0f) {
            // ---- single-window additive scan; terms in [2^-57, 2^63], no FTZ ----
            // K = upper bound of scores - 63:  c>0 -> c*umx;  c<0 -> 0 (since scores <= 0)
            const float K = ((ch > 0.0f) ? ch * umx : 0.0f) - 63.0f;
            float e0 = ex2(fmaf(ch, u0, -K));
            float e1 = ex2(fmaf(ch, u1, -K));
            float e2 = ex2(fmaf(ch, u2, -K));
            float e3 = ex2(fmaf(ch, u3, -K));
            float n0 = e0*xc0, n1 = e1*xc1, n2 = e2*xc2, n3 = e3*xc3;

            float d01 = e0 + e1, m01 = n0 + n1;
            float d012 = d01 + e2, m012 = m01 + n2;
            float dT = d012 + e3, mT = m012 + n3;

            float sd = dT, sn = mT;
            #pragma unroll
            for (int o = 1; o < 32; o <<= 1) {
                float ud = __shfl_up_sync(0xffffffffu, sd, o);
                float un = __shfl_up_sync(0xffffffffu, sn, o);
                if (lid >= o) { sd += ud; sn += un; }
            }
            float Pd = sd - dT;   // exclusive prefix by subtraction
            float Pn = sn - mT;

            py0 = __fdividef(Pn, Pd + 1e-37f);   // lane0: 0/eps = 0
            py1 = __fdividef(Pn + n0,   Pd + e0);
            py2 = __fdividef(Pn + m01,  Pd + d01);
            py3 = __fdividef(Pn + m012, Pd + d012);
        } else {
            // ---- exact monoid fallback (numerators already cf-scaled) ----
            OS a0 = { ch*u0, 1.0f, xc0 };
            OS a1 = comb(a0, { ch*u1, 1.0f, xc1 });
            OS a2 = comb(a1, { ch*u2, 1.0f, xc2 });
            OS a3 = comb(a2, { ch*u3, 1.0f, xc3 });
            OS agg = a3;
            #pragma unroll
            for (int o = 1; o < 32; o <<= 1) {
                OS up;
                up.m = __shfl_up_sync(0xffffffffu, agg.m, o);
                up.d = __shfl_up_sync(0xffffffffu, agg.d, o);
                up.n = __shfl_up_sync(0xffffffffu, agg.n, o);
                if (lid >= o) agg = comb(up, agg);
            }
            OS P;
            P.m = __shfl_up_sync(0xffffffffu, agg.m, 1);
            P.d = __shfl_up_sync(0xffffffffu, agg.d, 1);
            P.n = __shfl_up_sync(0xffffffffu, agg.n, 1);
            if (lid == 0) { P.m = -1e30f; P.d = 0.0f; P.n = 0.0f; }
            OS q1 = comb(P, a0);
            OS q2 = comb(P, a1);
            OS q3 = comb(P, a2);
            py0 = (lid == 0) ? 0.0f : __fdividef(P.n, P.d);
            py1 = __fdividef(q1.n, q1.d);
            py2 = __fdividef(q2.n, q2.d);
            py3 = __fdividef(q3.n, q3.d);
        }

        // ---- position-split epilogue ----
        reinterpret_cast<float4*>(ps[wr])[lid] = make_float4(py0, py1, py2, py3);
        __syncthreads();

        if (tid < NT) {
            const int p = tid;
            float y = bp_e[l];
            #pragma unroll
            for (int w = 0; w < NH; ++w) y += ps[w][p];

            float f = b2_e[l];
            #pragma unroll
            for (int k = 0; k < 4; ++k)
                f = fmaf(fmaxf(fmaf(y, w1_e[l][k], b1_e[l][k]), 0.0f), w2_e[l][k], f);
            float xn = y + f;

            if (l == NL - 1) {
                out[batch * NT + p] = fmaf(xn, wlm, blm);   // direct write, no final bar
            } else {
                xs[p] = xn;
            }
        }

        if (l < NL - 1) {
            __syncthreads();
            float4 xn = reinterpret_cast<const float4*>(xs)[lid];
            x0 = xn.x; x1 = xn.y; x2 = xn.z; x3 = xn.w;
        }
    }
}

extern "C" void kernel_launch(void* const* d_in, const int* in_sizes, int n_in,
                              void* d_out, int out_size) {
    (void)in_sizes; (void)n_in; (void)out_size;
    cat_kernel<<<512, 256>>>(
        (const float*)d_in[0],  // X
        (const float*)d_in[1],  // wk
        (const float*)d_in[2],  // wq
        (const float*)d_in[3],  // wv
        (const float*)d_in[4],  // Wp
        (const float*)d_in[5],  // bp
        (const float*)d_in[6],  // W1
        (const float*)d_in[7],  // b1
        (const float*)d_in[8],  // W2
        (const float*)d_in[9],  // b2
        (const float*)d_in[10], // w_lm
        (const float*)d_in[11], // b_lm
        (float*)d_out);
}